// round 6
// baseline (speedup 1.0000x reference)
#include <cuda_runtime.h>
#include <cstdint>
#include <cstddef>

// ---------------------------------------------------------------------------
// BlocDiagLinear: out[b, n*128+r] = sum_c x[b, n*128+c] * blocks[n, r, c]
// 64 independent GEMMs (M=4096, N=128, K=128), fp32 in/out.
// tcgen05 is unavailable (harness targets compute_103, not compute_103a), so
// we use legacy tensor cores: mma.sync.m16n8k8 tf32 with fp32 accumulate.
//
// Grid (64, 32): CTA tile M=128, N=128, K processed in 2 halves of 64 so the
// smem footprint (69.6 KB) allows 2 CTAs/SM for load/compute overlap.
// 8 warps in a 4(M) x 2(N) grid; warp tile 32x64; fp32 accum in registers.
// ---------------------------------------------------------------------------

static constexpr int THREADS = 256;
static constexpr int PADS   = 68;                      // smem row stride (floats): 64 + 4 pad
static constexpr int SMEM_BYTES = 2 * 128 * PADS * 4;  // A + B buffers = 69632

__device__ __forceinline__ uint32_t f2tf32(float f) {
    uint32_t r;
    asm("cvt.rna.tf32.f32 %0, %1;" : "=r"(r) : "f"(f));
    return r;
}

__global__ void __launch_bounds__(THREADS, 2)
bdl_mma_kernel(const float* __restrict__ x,
               const float* __restrict__ blocks,
               float* __restrict__ out)
{
    extern __shared__ uint32_t smem[];
    uint32_t* As = smem;                 // 128 rows (M) x 64 cols (K), stride PADS
    uint32_t* Bs = smem + 128 * PADS;    // 128 rows (N) x 64 cols (K), stride PADS

    const int tid  = threadIdx.x;
    const int wid  = tid >> 5;
    const int lane = tid & 31;
    const int g    = lane >> 2;          // 0..7
    const int tig  = lane & 3;           // 0..3

    const int n  = blockIdx.x;           // diagonal block 0..63
    const int m0 = blockIdx.y * 128;     // batch tile start

    const int mrow = (wid >> 1) * 32;    // warp M offset within tile
    const int ncol = (wid & 1) * 64;     // warp N offset within tile

    float acc[2][8][4];
    #pragma unroll
    for (int i = 0; i < 2; i++)
        #pragma unroll
        for (int j = 0; j < 8; j++)
            #pragma unroll
            for (int v = 0; v < 4; v++)
                acc[i][j][v] = 0.0f;

    #pragma unroll
    for (int kh = 0; kh < 2; kh++) {
        if (kh) __syncthreads();         // protect smem reuse from phase 0 readers

        // ---- Stage A: x[m0..m0+128, n*128 + kh*64 ..+64], tf32-rounded ----
        {
            const float* xg = x + (size_t)m0 * 8192 + n * 128 + kh * 64;
            #pragma unroll
            for (int it = 0; it < 8; it++) {
                const int j   = tid + it * 256;
                const int row = j >> 4;
                const int c4  = (j & 15) * 4;
                float4 v = *reinterpret_cast<const float4*>(xg + (size_t)row * 8192 + c4);
                uint32_t* d = &As[row * PADS + c4];
                d[0] = f2tf32(v.x); d[1] = f2tf32(v.y);
                d[2] = f2tf32(v.z); d[3] = f2tf32(v.w);
            }
        }
        // ---- Stage B: blocks[n, 0..128, kh*64 ..+64], tf32-rounded ----
        {
            const float* bg = blocks + (size_t)n * 16384 + kh * 64;
            #pragma unroll
            for (int it = 0; it < 8; it++) {
                const int j   = tid + it * 256;
                const int row = j >> 4;
                const int c4  = (j & 15) * 4;
                float4 v = *reinterpret_cast<const float4*>(bg + row * 128 + c4);
                uint32_t* d = &Bs[row * PADS + c4];
                d[0] = f2tf32(v.x); d[1] = f2tf32(v.y);
                d[2] = f2tf32(v.z); d[3] = f2tf32(v.w);
            }
        }
        __syncthreads();

        // ---- Compute: 8 k-steps of m16n8k8 tf32 mma ----
        #pragma unroll
        for (int kk = 0; kk < 8; kk++) {
            const int k0 = kk * 8;

            uint32_t a[2][4];
            #pragma unroll
            for (int i = 0; i < 2; i++) {
                const int r = mrow + 16 * i + g;
                a[i][0] = As[r * PADS + k0 + tig];
                a[i][1] = As[(r + 8) * PADS + k0 + tig];
                a[i][2] = As[r * PADS + k0 + tig + 4];
                a[i][3] = As[(r + 8) * PADS + k0 + tig + 4];
            }

            #pragma unroll
            for (int jj = 0; jj < 8; jj++) {
                const int br = (ncol + 8 * jj + g) * PADS + k0 + tig;
                const uint32_t b0 = Bs[br];
                const uint32_t b1 = Bs[br + 4];
                #pragma unroll
                for (int i = 0; i < 2; i++) {
                    asm volatile(
                        "mma.sync.aligned.m16n8k8.row.col.f32.tf32.tf32.f32 "
                        "{%0,%1,%2,%3}, {%4,%5,%6,%7}, {%8,%9}, {%0,%1,%2,%3};"
                        : "+f"(acc[i][jj][0]), "+f"(acc[i][jj][1]),
                          "+f"(acc[i][jj][2]), "+f"(acc[i][jj][3])
                        : "r"(a[i][0]), "r"(a[i][1]), "r"(a[i][2]), "r"(a[i][3]),
                          "r"(b0), "r"(b1));
                }
            }
        }
    }

    // ---- Epilogue: register accum -> gmem (float2 stores) ----
    // D frag: d0=D[g][2*tig], d1=D[g][2*tig+1], d2=D[g+8][2*tig], d3=D[g+8][2*tig+1]
    float* obase = out + (size_t)m0 * 8192 + n * 128;
    #pragma unroll
    for (int i = 0; i < 2; i++) {
        const int r0 = mrow + 16 * i + g;
        #pragma unroll
        for (int jj = 0; jj < 8; jj++) {
            const int c = ncol + 8 * jj + 2 * tig;
            float2 v0 = make_float2(acc[i][jj][0], acc[i][jj][1]);
            *reinterpret_cast<float2*>(obase + (size_t)r0 * 8192 + c) = v0;
            float2 v1 = make_float2(acc[i][jj][2], acc[i][jj][3]);
            *reinterpret_cast<float2*>(obase + (size_t)(r0 + 8) * 8192 + c) = v1;
        }
    }
}

extern "C" void kernel_launch(void* const* d_in, const int* in_sizes, int n_in,
                              void* d_out, int out_size)
{
    (void)in_sizes; (void)n_in; (void)out_size;
    const float* x      = (const float*)d_in[0];   // [4096, 8192]
    const float* blocks = (const float*)d_in[1];   // [64, 128, 128]
    float* out          = (float*)d_out;           // [4096, 8192]

    cudaFuncSetAttribute(bdl_mma_kernel,
                         cudaFuncAttributeMaxDynamicSharedMemorySize, SMEM_BYTES);

    dim3 grid(64, 32, 1);   // (diagonal block n, batch tile)
    bdl_mma_kernel<<<grid, THREADS, SMEM_BYTES>>>(x, blocks, out);
}

// round 8
// speedup vs baseline: 1.3712x; 1.3712x over previous
#include <cuda_runtime.h>
#include <cstdint>
#include <cstddef>

// ---------------------------------------------------------------------------
// BlocDiagLinear: out[b, n*128+r] = sum_c x[b, n*128+c] * blocks[n, r, c]
// 64 GEMMs (M=4096, N=128, K=128) fp32. tcgen05 unavailable (compute_103
// virtual arch) -> mma.sync.m16n8k8.tf32 with fp32 accumulate.
//
// R7 structure: grid (64, 32), CTA tile 128x128x128.
//  - K split into 4 chunks of 32; cp.async 3-stage ring (A+B, 32KB/stage).
//  - XOR-swizzled smem (16B atom: c ^= row&7), ldmatrix.x4 fragment loads.
//  - blocks pre-rounded to tf32 (rna) by a tiny pre-kernel into scratch;
//    A fragments rounded with cvt.rna post-ldmatrix. Same precision as R6.
// ---------------------------------------------------------------------------

static constexpr int THREADS = 256;
static constexpr int STAGE_BYTES = 32768;            // A 16KB + B 16KB
static constexpr int SMEM_BYTES  = 3 * STAGE_BYTES;  // 98304 -> 2 CTAs/SM

__device__ float g_blocks_r[64 * 128 * 128];         // rna-rounded blocks (4MB)

__device__ __forceinline__ uint32_t smem_u32(const void* p) {
    uint32_t a;
    asm("{ .reg .u64 t; cvta.to.shared.u64 t, %1; cvt.u32.u64 %0, t; }"
        : "=r"(a) : "l"(p));
    return a;
}

__device__ __forceinline__ uint32_t f2tf32(float f) {
    uint32_t r;
    asm("cvt.rna.tf32.f32 %0, %1;" : "=r"(r) : "f"(f));
    return r;
}

// -------------------- pre-kernel: round blocks to tf32 ---------------------
__global__ void __launch_bounds__(256)
round_blocks_kernel(const float* __restrict__ blocks)
{
    const int i = (blockIdx.x * 256 + threadIdx.x) * 4;   // 1024 blocks cover 1M
    float4 v = *reinterpret_cast<const float4*>(blocks + i);
    float4 o;
    o.x = __uint_as_float(f2tf32(v.x));
    o.y = __uint_as_float(f2tf32(v.y));
    o.z = __uint_as_float(f2tf32(v.z));
    o.w = __uint_as_float(f2tf32(v.w));
    *reinterpret_cast<float4*>(g_blocks_r + i) = o;
}

// -------------------- main kernel ------------------------------------------

// Issue one K-chunk stage (A: x tile, B: rounded blocks) via cp.async.
__device__ __forceinline__ void issue_stage(uint32_t sbase,
                                            const float* __restrict__ xg,
                                            const float* __restrict__ bgr,
                                            int s)
{
    #pragma unroll
    for (int it = 0; it < 4; it++) {
        const int j   = threadIdx.x + it * 256;   // 0..1023 int4 slots
        const int row = j >> 3;                   // 0..127
        const int c   = j & 7;                    // int4 col within 128B row
        const uint32_t sw = (uint32_t)((c ^ (row & 7)) << 4);
        const uint32_t dA = sbase + row * 128 + sw;
        const float* sA = xg + (size_t)row * 8192 + s * 32 + c * 4;
        asm volatile("cp.async.cg.shared.global [%0], [%1], 16;"
                     :: "r"(dA), "l"(sA));
        const uint32_t dB = sbase + 16384 + row * 128 + sw;
        const float* sB = bgr + row * 128 + s * 32 + c * 4;
        asm volatile("cp.async.cg.shared.global [%0], [%1], 16;"
                     :: "r"(dB), "l"(sB));
    }
    asm volatile("cp.async.commit_group;" ::: "memory");
}

__device__ __forceinline__ void compute_stage(uint32_t abase, uint32_t bbase,
                                              int mrow, int ncol, int lane,
                                              float acc[2][8][4])
{
    const int t4 = lane >> 3;     // tile index within ldmatrix.x4
    const int tr = lane & 7;      // row within tile

    #pragma unroll
    for (int kk = 0; kk < 4; kk++) {
        // ---- A fragments: 2 x ldmatrix.x4 (rows mrow+16i, k cols 8*kk..+8)
        uint32_t a[2][4];
        #pragma unroll
        for (int i = 0; i < 2; i++) {
            const int r = mrow + 16 * i + ((t4 & 1) << 3) + tr;
            const int c = 2 * kk + (t4 >> 1);
            const uint32_t addr = abase + r * 128 + ((uint32_t)(c ^ (r & 7)) << 4);
            asm volatile(
                "ldmatrix.sync.aligned.m8n8.x4.shared.b16 {%0,%1,%2,%3}, [%4];"
                : "=r"(a[i][0]), "=r"(a[i][1]), "=r"(a[i][2]), "=r"(a[i][3])
                : "r"(addr));
        }
        // rna-round A to tf32 (B already rounded by pre-kernel)
        #pragma unroll
        for (int i = 0; i < 2; i++)
            #pragma unroll
            for (int q = 0; q < 4; q++)
                a[i][q] = f2tf32(__uint_as_float(a[i][q]));

        // ---- B fragments: 4 x ldmatrix.x4 cover jj pairs {0,1},{2,3},{4,5},{6,7}
        uint32_t b[8][2];
        #pragma unroll
        for (int p = 0; p < 4; p++) {
            const int rn = ncol + (2 * p + (t4 >> 1)) * 8 + tr;
            const int c  = 2 * kk + (t4 & 1);
            const uint32_t addr = bbase + rn * 128 + ((uint32_t)(c ^ (rn & 7)) << 4);
            asm volatile(
                "ldmatrix.sync.aligned.m8n8.x4.shared.b16 {%0,%1,%2,%3}, [%4];"
                : "=r"(b[2 * p][0]), "=r"(b[2 * p][1]),
                  "=r"(b[2 * p + 1][0]), "=r"(b[2 * p + 1][1])
                : "r"(addr));
        }

        // ---- 16 mma per k-step
        #pragma unroll
        for (int jj = 0; jj < 8; jj++)
            #pragma unroll
            for (int i = 0; i < 2; i++) {
                asm volatile(
                    "mma.sync.aligned.m16n8k8.row.col.f32.tf32.tf32.f32 "
                    "{%0,%1,%2,%3}, {%4,%5,%6,%7}, {%8,%9}, {%0,%1,%2,%3};"
                    : "+f"(acc[i][jj][0]), "+f"(acc[i][jj][1]),
                      "+f"(acc[i][jj][2]), "+f"(acc[i][jj][3])
                    : "r"(a[i][0]), "r"(a[i][1]), "r"(a[i][2]), "r"(a[i][3]),
                      "r"(b[jj][0]), "r"(b[jj][1]));
            }
    }
}

__global__ void __launch_bounds__(THREADS, 2)
bdl_mma_kernel(const float* __restrict__ x,
               float* __restrict__ out)
{
    extern __shared__ char smem[];
    const uint32_t sb = smem_u32(smem);

    const int tid  = threadIdx.x;
    const int wid  = tid >> 5;
    const int lane = tid & 31;
    const int g    = lane >> 2;
    const int tig  = lane & 3;

    const int n  = blockIdx.x;
    const int m0 = blockIdx.y * 128;

    const int mrow = (wid >> 1) * 32;
    const int ncol = (wid & 1) * 64;

    const float* xg  = x + (size_t)m0 * 8192 + n * 128;
    const float* bgr = g_blocks_r + (size_t)n * 16384;

    float acc[2][8][4];
    #pragma unroll
    for (int i = 0; i < 2; i++)
        #pragma unroll
        for (int j = 0; j < 8; j++)
            #pragma unroll
            for (int v = 0; v < 4; v++)
                acc[i][j][v] = 0.0f;

    // ---- prologue: fill ring with stages 0..2 ----
    issue_stage(sb + 0 * STAGE_BYTES, xg, bgr, 0);
    issue_stage(sb + 1 * STAGE_BYTES, xg, bgr, 1);
    issue_stage(sb + 2 * STAGE_BYTES, xg, bgr, 2);

    // ---- stage 0 ----
    asm volatile("cp.async.wait_group 2;" ::: "memory");
    __syncthreads();
    compute_stage(sb + 0 * STAGE_BYTES, sb + 0 * STAGE_BYTES + 16384,
                  mrow, ncol, lane, acc);
    __syncthreads();                       // buf0 free before reuse
    issue_stage(sb + 0 * STAGE_BYTES, xg, bgr, 3);

    // ---- stage 1 ----
    asm volatile("cp.async.wait_group 2;" ::: "memory");
    __syncthreads();
    compute_stage(sb + 1 * STAGE_BYTES, sb + 1 * STAGE_BYTES + 16384,
                  mrow, ncol, lane, acc);

    // ---- stage 2 ----
    asm volatile("cp.async.wait_group 1;" ::: "memory");
    __syncthreads();
    compute_stage(sb + 2 * STAGE_BYTES, sb + 2 * STAGE_BYTES + 16384,
                  mrow, ncol, lane, acc);

    // ---- stage 3 (in buf0) ----
    asm volatile("cp.async.wait_group 0;" ::: "memory");
    __syncthreads();
    compute_stage(sb + 0 * STAGE_BYTES, sb + 0 * STAGE_BYTES + 16384,
                  mrow, ncol, lane, acc);

    // ---- epilogue: float2 stores (each STG fills whole 32B sectors) ----
    float* obase = out + (size_t)m0 * 8192 + n * 128;
    #pragma unroll
    for (int i = 0; i < 2; i++) {
        const int r0 = mrow + 16 * i + g;
        #pragma unroll
        for (int jj = 0; jj < 8; jj++) {
            const int c = ncol + 8 * jj + 2 * tig;
            *reinterpret_cast<float2*>(obase + (size_t)r0 * 8192 + c) =
                make_float2(acc[i][jj][0], acc[i][jj][1]);
            *reinterpret_cast<float2*>(obase + (size_t)(r0 + 8) * 8192 + c) =
                make_float2(acc[i][jj][2], acc[i][jj][3]);
        }
    }
}

extern "C" void kernel_launch(void* const* d_in, const int* in_sizes, int n_in,
                              void* d_out, int out_size)
{
    (void)in_sizes; (void)n_in; (void)out_size;
    const float* x      = (const float*)d_in[0];   // [4096, 8192]
    const float* blocks = (const float*)d_in[1];   // [64, 128, 128]
    float* out          = (float*)d_out;           // [4096, 8192]

    round_blocks_kernel<<<1024, 256>>>(blocks);

    cudaFuncSetAttribute(bdl_mma_kernel,
                         cudaFuncAttributeMaxDynamicSharedMemorySize, SMEM_BYTES);
    dim3 grid(64, 32, 1);
    bdl_mma_kernel<<<grid, THREADS, SMEM_BYTES>>>(x, out);
}